// round 4
// baseline (speedup 1.0000x reference)
#include <cuda_runtime.h>

// Problem constants (B, S, K) = (512, 2048, 17)
#define BB 512
#define SS 2048
#define KK 17
#define SK (SS * KK)
#define TILE 32            // scan steps per emission tile
#define TILEF (TILE * KK)  // 544 floats = 2176 B per tile
#define SEQ_PER_BLK 4

__device__ float g_part[BB];   // per-sequence (logZ - numerator)

__device__ __forceinline__ void cp16(void* smem, const void* gmem) {
    unsigned s = (unsigned)__cvta_generic_to_shared(smem);
    asm volatile("cp.async.cg.shared.global [%0], [%1], 16;\n" :: "r"(s), "l"(gmem));
}
#define CP_COMMIT() asm volatile("cp.async.commit_group;\n" ::: "memory")
#define CP_WAIT1()  asm volatile("cp.async.wait_group 1;\n" ::: "memory")

// copy one 544-float tile (136 x 16B) global -> shared via cp.async
__device__ __forceinline__ void load_tile(float* dst, const float* src, int lane) {
    #pragma unroll
    for (int r = 0; r < 4; r++)
        cp16(dst + (lane + 32 * r) * 4, src + (lane + 32 * r) * 4);
    if (lane < 8)
        cp16(dst + (128 + lane) * 4, src + (128 + lane) * 4);
}

__global__ __launch_bounds__(512) void crf_kernel(
    const float* __restrict__ em,      // [B,S,K]
    const float* __restrict__ startT,  // [K]
    const float* __restrict__ endT,    // [K]
    const float* __restrict__ trans,   // [K,K]
    const int*   __restrict__ labels,  // [B,S]
    const int*   __restrict__ attn,    // [B,S]
    float* __restrict__ out,           // [0]=loss, [1..]=emissions copy
    int copy_emissions)
{
    const int tid  = threadIdx.x;
    const int wid  = tid >> 5;
    const int lane = tid & 31;

    // --- warps 4..15: stream-copy this block's 4 sequences of emissions ---
    if (wid >= 4) {
        if (copy_emissions) {
            const size_t base = (size_t)blockIdx.x * SEQ_PER_BLK * SK;
            const float4* s4 = (const float4*)(em + base);
            float* dst = out + 1 + base;             // 4B-aligned only -> scalar stores
            const int n4 = SEQ_PER_BLK * SK / 4;     // 34816 float4s
            #pragma unroll 2
            for (int i = tid - 128; i < n4; i += 384) {
                float4 v = s4[i];
                dst[4 * i + 0] = v.x;
                dst[4 * i + 1] = v.y;
                dst[4 * i + 2] = v.z;
                dst[4 * i + 3] = v.w;
            }
        }
        return;
    }

    // --- warps 0..3: each scans one sequence (one warp per SMSP) ---
    const int b = blockIdx.x * SEQ_PER_BLK + wid;
    const float* emb = em + (size_t)b * SK;
    const int*   lab = labels + (size_t)b * SS;
    const int*   msk = attn   + (size_t)b * SS;

    __shared__ __align__(16) float ebuf[SEQ_PER_BLK][2][TILEF];
    __shared__ unsigned mask_bits[SEQ_PER_BLK][SS / 32];

    // exp(transitions) column for this lane's state j (tiny, L1/L2 resident)
    float w[KK];
    #pragma unroll
    for (int i = 0; i < KK; i++)
        w[i] = (lane < KK) ? __expf(__ldg(&trans[i * KK + lane])) : 0.0f;

    // ---- numerator pass + mask bit packing + seq-end stats ----
    float numv = 0.0f;
    int cnt = 0, lastidx = 0;
    for (int t = lane; t < SS; t += 32) {
        int lt = lab[t];
        int m  = (msk[t] != 0) && (lt >= 0);
        unsigned bal = __ballot_sync(0xffffffffu, m);
        if (lane == 0) mask_bits[wid][t >> 5] = bal;
        if (m) {
            cnt++;
            lastidx = t;
            if (t > 0) {
                int ltc = (lt == -100) ? 0 : lt;
                int lp  = lab[t - 1];
                int lpc = (lp == -100) ? 0 : lp;
                numv += __ldg(&trans[lpc * KK + ltc]) + emb[t * KK + ltc];
            }
        }
    }
    #pragma unroll
    for (int o = 16; o; o >>= 1) {
        numv += __shfl_xor_sync(0xffffffffu, numv, o);
        cnt  += __shfl_xor_sync(0xffffffffu, cnt,  o);
        lastidx = max(lastidx, __shfl_xor_sync(0xffffffffu, lastidx, o));
    }
    {
        int l0  = lab[0];
        int l0c = (l0 == -100) ? 0 : l0;
        int se  = max(cnt - 1, 0);
        int le  = lab[se];
        int lec = (le == -100) ? 0 : le;
        numv += startT[l0c] + emb[l0c] + endT[lec];
    }
    __syncwarp();   // mask_bits visible within this warp

    // ---- alpha_0 in linear space, carried log-scale M ----
    float al = (lane < KK) ? (startT[lane] + emb[lane]) : -1e30f;
    float M = al;
    #pragma unroll
    for (int o = 16; o; o >>= 1)
        M = fmaxf(M, __shfl_xor_sync(0xffffffffu, M, o));
    float a = (lane < KK) ? __expf(al - M) : 0.0f;

    const int lasttile = lastidx / TILE;

    // prologue: async-load tiles 0 and 1 (2 committed groups invariant)
    load_tile(ebuf[wid][0], emb, lane);
    CP_COMMIT();
    if (lasttile >= 1)
        load_tile(ebuf[wid][1], emb + TILEF, lane);
    CP_COMMIT();

    // ---- forward scan over uniform 32-step tiles ----
    for (int tb = 0; tb <= lasttile; tb++) {
        CP_WAIT1();            // tile tb complete (<=1 group pending)
        __syncwarp();          // cross-lane visibility of cp.async data

        const float* eb = ebuf[wid][tb & 1];
        unsigned mword = mask_bits[wid][tb];
        if (tb == 0) mword &= ~1u;      // step t=0 does not exist

        #pragma unroll 8
        for (int tt = 0; tt < TILE; ++tt) {
            float e = eb[tt * KK + lane];   // lanes>=17 read other data; harmless
            float g = __expf(e);

            // broadcast previous alpha into 17 independent registers
            float rr[KK];
            #pragma unroll
            for (int i = 0; i < KK; i++)
                rr[i] = __shfl_sync(0xffffffffu, a, i);

            float s0 = rr[0] * w[0];
            float s1 = rr[1] * w[1];
            float s2 = rr[2] * w[2];
            float s3 = rr[3] * w[3];
            s0 = fmaf(rr[4],  w[4],  s0);
            s1 = fmaf(rr[5],  w[5],  s1);
            s2 = fmaf(rr[6],  w[6],  s2);
            s3 = fmaf(rr[7],  w[7],  s3);
            s0 = fmaf(rr[8],  w[8],  s0);
            s1 = fmaf(rr[9],  w[9],  s1);
            s2 = fmaf(rr[10], w[10], s2);
            s3 = fmaf(rr[11], w[11], s3);
            s0 = fmaf(rr[12], w[12], s0);
            s1 = fmaf(rr[13], w[13], s1);
            s2 = fmaf(rr[14], w[14], s2);
            s3 = fmaf(rr[15], w[15], s3);
            s0 = fmaf(rr[16], w[16], s0);
            float s = (s0 + s1) + (s2 + s3);

            bool m = (mword >> tt) & 1u;
            float anew = s * g;
            a = m ? anew : a;

            if ((tt & 7) == 0) {
                // renorm by exact power of two from max(previous alpha) = max(rr)
                float m0 = fmaxf(rr[0],  rr[1]);
                float m1 = fmaxf(rr[2],  rr[3]);
                float m2 = fmaxf(rr[4],  rr[5]);
                float m3 = fmaxf(rr[6],  rr[7]);
                m0 = fmaxf(m0, fmaxf(rr[8],  rr[9]));
                m1 = fmaxf(m1, fmaxf(rr[10], rr[11]));
                m2 = fmaxf(m2, fmaxf(rr[12], rr[13]));
                m3 = fmaxf(m3, fmaxf(rr[14], rr[15]));
                float mx = fmaxf(fmaxf(m0, m1), fmaxf(fmaxf(m2, m3), rr[16]));
                int e2 = (__float_as_int(mx) >> 23) - 127;       // floor(log2 mx)
                float scale = __int_as_float((127 - e2) << 23);  // exact 2^-e2
                a *= scale;
                M += (float)e2 * 0.6931471805599453f;
            }
        }

        // start async load of tile tb+2, keep 2-group invariant
        if (tb + 2 <= lasttile)
            load_tile(ebuf[wid][tb & 1], emb + (size_t)(tb + 2) * TILEF, lane);
        CP_COMMIT();
    }

    // ---- log_z = M + log( sum_j a_j * exp(end_j) ) ----
    float zterm = (lane < KK) ? a * __expf(endT[lane]) : 0.0f;
    #pragma unroll
    for (int o = 16; o; o >>= 1)
        zterm += __shfl_xor_sync(0xffffffffu, zterm, o);
    float logz = M + __logf(zterm);

    if (lane == 0)
        g_part[b] = logz - numv;
}

__global__ void reduce_kernel(float* __restrict__ out)
{
    __shared__ float sh[128];
    int t = threadIdx.x;
    float v = 0.0f;
    #pragma unroll
    for (int i = 0; i < BB / 128; i++)
        v += g_part[t + 128 * i];
    sh[t] = v;
    __syncthreads();
    #pragma unroll
    for (int s2 = 64; s2; s2 >>= 1) {
        if (t < s2) sh[t] += sh[t + s2];
        __syncthreads();
    }
    if (t == 0) out[0] = sh[0] * (1.0f / (float)BB);
}

extern "C" void kernel_launch(void* const* d_in, const int* in_sizes, int n_in,
                              void* d_out, int out_size)
{
    const float* em  = (const float*)d_in[0];
    const float* st  = (const float*)d_in[1];
    const float* en  = (const float*)d_in[2];
    const float* tr  = (const float*)d_in[3];
    const int*   lab = (const int*)d_in[4];
    const int*   att = (const int*)d_in[5];
    float* out = (float*)d_out;

    int copy = (out_size > in_sizes[0]) ? 1 : 0;

    crf_kernel<<<BB / SEQ_PER_BLK, 512>>>(em, st, en, tr, lab, att, out, copy);
    reduce_kernel<<<1, 128>>>(out);
}

// round 5
// speedup vs baseline: 1.2926x; 1.2926x over previous
#include <cuda_runtime.h>

// Problem constants (B, S, K) = (512, 2048, 17)
#define BB 512
#define SS 2048
#define KK 17
#define SK (SS * KK)
#define TILE 32            // scan steps per emission tile
#define TILEF (TILE * KK)  // 544 floats = 2176 B per tile
#define SEQ_PER_BLK 4

__device__ float g_part[BB];   // per-sequence (logZ - numerator)

__device__ __forceinline__ void cp16(void* smem, const void* gmem) {
    unsigned s = (unsigned)__cvta_generic_to_shared(smem);
    asm volatile("cp.async.cg.shared.global [%0], [%1], 16;\n" :: "r"(s), "l"(gmem));
}
#define CP_COMMIT() asm volatile("cp.async.commit_group;\n" ::: "memory")
#define CP_WAIT1()  asm volatile("cp.async.wait_group 1;\n" ::: "memory")

// copy one 544-float tile (136 x 16B) global -> shared via cp.async
__device__ __forceinline__ void load_tile(float* dst, const float* src, int lane) {
    #pragma unroll
    for (int r = 0; r < 4; r++)
        cp16(dst + (lane + 32 * r) * 4, src + (lane + 32 * r) * 4);
    if (lane < 8)
        cp16(dst + (128 + lane) * 4, src + (128 + lane) * 4);
}

__global__ __launch_bounds__(512) void crf_kernel(
    const float* __restrict__ em,      // [B,S,K]
    const float* __restrict__ startT,  // [K]
    const float* __restrict__ endT,    // [K]
    const float* __restrict__ trans,   // [K,K]
    const int*   __restrict__ labels,  // [B,S]
    const int*   __restrict__ attn,    // [B,S]
    float* __restrict__ out,           // [0]=loss, [1..]=emissions copy
    int copy_emissions)
{
    const int tid  = threadIdx.x;
    const int wid  = tid >> 5;
    const int lane = tid & 31;

    // --- warps 4..15: stream-copy this block's 4 sequences of emissions ---
    if (wid >= 4) {
        if (copy_emissions) {
            const size_t base = (size_t)blockIdx.x * SEQ_PER_BLK * SK;
            const float4* s4 = (const float4*)(em + base);
            float* dst = out + 1 + base;             // 4B-aligned only -> scalar stores
            const int n4 = SEQ_PER_BLK * SK / 4;     // 34816 float4s
            #pragma unroll 2
            for (int i = tid - 128; i < n4; i += 384) {
                float4 v = s4[i];
                dst[4 * i + 0] = v.x;
                dst[4 * i + 1] = v.y;
                dst[4 * i + 2] = v.z;
                dst[4 * i + 3] = v.w;
            }
        }
        return;
    }

    // --- warps 0..3: each scans one sequence (one warp per SMSP) ---
    const int b = blockIdx.x * SEQ_PER_BLK + wid;
    const float* emb = em + (size_t)b * SK;
    const int*   lab = labels + (size_t)b * SS;
    const int*   msk = attn   + (size_t)b * SS;

    __shared__ __align__(16) float ebuf[SEQ_PER_BLK][2][TILEF];
    __shared__ __align__(16) float arow[SEQ_PER_BLK][2][32];   // alpha broadcast rows
    __shared__ unsigned mask_bits[SEQ_PER_BLK][SS / 32];

    // exp(transitions) column for this lane's state j (tiny, L1/L2 resident)
    float w[KK];
    #pragma unroll
    for (int i = 0; i < KK; i++)
        w[i] = (lane < KK) ? __expf(__ldg(&trans[i * KK + lane])) : 0.0f;

    // ---- numerator pass + mask bit packing + seq-end stats ----
    float numv = 0.0f;
    int cnt = 0, lastidx = 0;
    for (int t = lane; t < SS; t += 32) {
        int lt = lab[t];
        int m  = (msk[t] != 0) && (lt >= 0);
        unsigned bal = __ballot_sync(0xffffffffu, m);
        if (lane == 0) mask_bits[wid][t >> 5] = bal;
        if (m) {
            cnt++;
            lastidx = t;
            if (t > 0) {
                int ltc = (lt == -100) ? 0 : lt;
                int lp  = lab[t - 1];
                int lpc = (lp == -100) ? 0 : lp;
                numv += __ldg(&trans[lpc * KK + ltc]) + emb[t * KK + ltc];
            }
        }
    }
    #pragma unroll
    for (int o = 16; o; o >>= 1) {
        numv += __shfl_xor_sync(0xffffffffu, numv, o);
        cnt  += __shfl_xor_sync(0xffffffffu, cnt,  o);
        lastidx = max(lastidx, __shfl_xor_sync(0xffffffffu, lastidx, o));
    }
    {
        int l0  = lab[0];
        int l0c = (l0 == -100) ? 0 : l0;
        int se  = max(cnt - 1, 0);
        int le  = lab[se];
        int lec = (le == -100) ? 0 : le;
        numv += startT[l0c] + emb[l0c] + endT[lec];
    }
    __syncwarp();   // mask_bits visible within this warp

    // ---- alpha_0 in linear space, carried log-scale M ----
    float al = (lane < KK) ? (startT[lane] + emb[lane]) : -1e30f;
    float M = al;
    #pragma unroll
    for (int o = 16; o; o >>= 1)
        M = fmaxf(M, __shfl_xor_sync(0xffffffffu, M, o));
    float a = (lane < KK) ? __expf(al - M) : 0.0f;

    const int lasttile = lastidx / TILE;

    // prologue: async-load tiles 0 and 1 (2 committed groups invariant)
    load_tile(ebuf[wid][0], emb, lane);
    CP_COMMIT();
    if (lasttile >= 1)
        load_tile(ebuf[wid][1], emb + TILEF, lane);
    CP_COMMIT();

    int cur = 0;

    // ---- forward scan over uniform 32-step tiles ----
    for (int tb = 0; tb <= lasttile; tb++) {
        CP_WAIT1();            // tile tb complete (<=1 group pending)
        __syncwarp();          // cross-lane visibility of cp.async data

        const float* eb = ebuf[wid][tb & 1];
        unsigned mword = mask_bits[wid][tb];
        if (tb == 0) mword &= ~1u;      // step t=0 does not exist

        #pragma unroll 8
        for (int tt = 0; tt < TILE; ++tt) {
            float e = eb[tt * KK + lane];   // lanes>=17 read other data; harmless
            float g = __expf(e);

            // broadcast previous alpha through shared memory (1 STS + 5 LDS)
            arow[wid][cur][lane] = a;       // lanes >=17 store junk; never read
            __syncwarp();
            const float* ar = arow[wid][cur];
            float4 v0 = *(const float4*)&ar[0];
            float4 v1 = *(const float4*)&ar[4];
            float4 v2 = *(const float4*)&ar[8];
            float4 v3 = *(const float4*)&ar[12];
            float  v16 = ar[16];
            cur ^= 1;

            float s0 = v0.x * w[0];
            float s1 = v0.y * w[1];
            float s2 = v0.z * w[2];
            float s3 = v0.w * w[3];
            s0 = fmaf(v1.x, w[4],  s0);
            s1 = fmaf(v1.y, w[5],  s1);
            s2 = fmaf(v1.z, w[6],  s2);
            s3 = fmaf(v1.w, w[7],  s3);
            s0 = fmaf(v2.x, w[8],  s0);
            s1 = fmaf(v2.y, w[9],  s1);
            s2 = fmaf(v2.z, w[10], s2);
            s3 = fmaf(v2.w, w[11], s3);
            s0 = fmaf(v3.x, w[12], s0);
            s1 = fmaf(v3.y, w[13], s1);
            s2 = fmaf(v3.z, w[14], s2);
            s3 = fmaf(v3.w, w[15], s3);
            s0 = fmaf(v16,  w[16], s0);
            float s = (s0 + s1) + (s2 + s3);

            bool m = (mword >> tt) & 1u;
            float anew = s * g;
            a = m ? anew : a;

            if ((tt & 7) == 0) {
                // renorm by exact power of two from max(previous alpha) = max(v*)
                float m0 = fmaxf(fmaxf(v0.x, v0.y), fmaxf(v0.z, v0.w));
                float m1 = fmaxf(fmaxf(v1.x, v1.y), fmaxf(v1.z, v1.w));
                float m2 = fmaxf(fmaxf(v2.x, v2.y), fmaxf(v2.z, v2.w));
                float m3 = fmaxf(fmaxf(v3.x, v3.y), fmaxf(v3.z, v3.w));
                float mx = fmaxf(fmaxf(m0, m1), fmaxf(fmaxf(m2, m3), v16));
                int e2 = (__float_as_int(mx) >> 23) - 127;       // floor(log2 mx)
                float scale = __int_as_float((127 - e2) << 23);  // exact 2^-e2
                a *= scale;
                M += (float)e2 * 0.6931471805599453f;
            }
        }

        // start async load of tile tb+2, keep 2-group invariant
        if (tb + 2 <= lasttile)
            load_tile(ebuf[wid][tb & 1], emb + (size_t)(tb + 2) * TILEF, lane);
        CP_COMMIT();
    }

    // ---- log_z = M + log( sum_j a_j * exp(end_j) ) ----
    float zterm = (lane < KK) ? a * __expf(endT[lane]) : 0.0f;
    #pragma unroll
    for (int o = 16; o; o >>= 1)
        zterm += __shfl_xor_sync(0xffffffffu, zterm, o);
    float logz = M + __logf(zterm);

    if (lane == 0)
        g_part[b] = logz - numv;
}

__global__ void reduce_kernel(float* __restrict__ out)
{
    __shared__ float sh[128];
    int t = threadIdx.x;
    float v = 0.0f;
    #pragma unroll
    for (int i = 0; i < BB / 128; i++)
        v += g_part[t + 128 * i];
    sh[t] = v;
    __syncthreads();
    #pragma unroll
    for (int s2 = 64; s2; s2 >>= 1) {
        if (t < s2) sh[t] += sh[t + s2];
        __syncthreads();
    }
    if (t == 0) out[0] = sh[0] * (1.0f / (float)BB);
}

extern "C" void kernel_launch(void* const* d_in, const int* in_sizes, int n_in,
                              void* d_out, int out_size)
{
    const float* em  = (const float*)d_in[0];
    const float* st  = (const float*)d_in[1];
    const float* en  = (const float*)d_in[2];
    const float* tr  = (const float*)d_in[3];
    const int*   lab = (const int*)d_in[4];
    const int*   att = (const int*)d_in[5];
    float* out = (float*)d_out;

    int copy = (out_size > in_sizes[0]) ? 1 : 0;

    crf_kernel<<<BB / SEQ_PER_BLK, 512>>>(em, st, en, tr, lab, att, out, copy);
    reduce_kernel<<<1, 128>>>(out);
}